// round 16
// baseline (speedup 1.0000x reference)
#include <cuda_runtime.h>
#include <cuda_bf16.h>
#include <math.h>

#define E_TOTAL 400000
#define NNODES  12500
#define T1      128
#define NTILES  3125
#define FULLC   25
#define MALL    19
#define NSPEC   90

typedef unsigned long long ull;
typedef unsigned int u32;

// ---------------- device scratch (static, no allocs)
__device__ float F_buf[(size_t)E_TOTAL * 320];
__device__ int   d_cnt[NNODES];
__device__ int   d_cur[NNODES];
__device__ int   d_offs[NNODES + 1];
__device__ int   d_eids[E_TOTAL];
__device__ float SPb[NSPEC * 64];
__device__ float RPb[NSPEC * 64];
__device__ __align__(16) unsigned char BimgP[8][20480];

// ---------------- f32x2 helpers
__device__ __forceinline__ ull pack2(float x) {
    ull r; asm("mov.b64 %0,{%1,%1};" : "=l"(r) : "f"(x)); return r;
}
__device__ __forceinline__ void fma2(ull& d, ull a, ull b) {
    asm("fma.rn.f32x2 %0,%1,%2,%0;" : "+l"(d) : "l"(a), "l"(b));
}
__device__ __forceinline__ float2 unpk(ull v) {
    float2 o; asm("mov.b64 {%0,%1},%2;" : "=f"(o.x), "=f"(o.y) : "l"(v)); return o;
}
__device__ __forceinline__ ull add2(ull a, ull b) {
    ull r; asm("add.rn.f32x2 %0,%1,%2;" : "=l"(r) : "l"(a), "l"(b)); return r;
}

// ---------------- HMMA helpers
__device__ __forceinline__ void hmma(float& d0, float& d1, float& d2, float& d3,
                                     u32 a0, u32 a1, u32 a2, u32 a3,
                                     u32 b0, u32 b1) {
    asm volatile("mma.sync.aligned.m16n8k16.row.col.f32.bf16.bf16.f32 "
        "{%0,%1,%2,%3}, {%4,%5,%6,%7}, {%8,%9}, {%0,%1,%2,%3};"
        : "+f"(d0), "+f"(d1), "+f"(d2), "+f"(d3)
        : "r"(a0), "r"(a1), "r"(a2), "r"(a3), "r"(b0), "r"(b1));
}
__device__ __forceinline__ void split2(float x, float y, u32& hi, u32& lo) {
    __nv_bfloat16 hx = __float2bfloat16(x);
    __nv_bfloat16 hy = __float2bfloat16(y);
    __nv_bfloat16 lx = __float2bfloat16(x - __bfloat162float(hx));
    __nv_bfloat16 ly = __float2bfloat16(y - __bfloat162float(hy));
    hi = (u32)__bfloat16_as_ushort(hx) | ((u32)__bfloat16_as_ushort(hy) << 16);
    lo = (u32)__bfloat16_as_ushort(lx) | ((u32)__bfloat16_as_ushort(ly) << 16);
}

// ---------------- prelude: species projection + histogram (fused)
__global__ void prep_kernel(const int* __restrict__ receivers,
                            const float* __restrict__ semb,
                            const float* __restrict__ remb,
                            const float* __restrict__ W1,
                            const float* __restrict__ b1)
{
    const int SPBLK = (NSPEC * 64 + 255) / 256;
    if (blockIdx.x < SPBLK) {
        int idx = blockIdx.x * 256 + threadIdx.x;
        if (idx < NSPEC * 64) {
            int s = idx >> 6, c = idx & 63;
            float sp = b1[c], rp = 0.0f;
            #pragma unroll 8
            for (int k = 0; k < 64; ++k) {
                sp += semb[s * 64 + k] * W1[(128 + k) * 64 + c];
                rp += remb[s * 64 + k] * W1[(192 + k) * 64 + c];
            }
            SPb[idx] = sp;
            RPb[idx] = rp;
        }
    } else {
        int e = (blockIdx.x - SPBLK) * 256 + threadIdx.x;
        if (e < E_TOTAL) atomicAdd(&d_cnt[receivers[e]], 1);
    }
}
__global__ void scan_kernel() {
    __shared__ int s[1024];
    const int CH = (NNODES + 1023) / 1024;
    int t = threadIdx.x;
    int base = t * CH;
    int loc[CH];
    int sum = 0;
    #pragma unroll
    for (int i = 0; i < CH; ++i) {
        int v = (base + i < NNODES) ? d_cnt[base + i] : 0;
        loc[i] = sum; sum += v;
    }
    s[t] = sum;
    __syncthreads();
    for (int off = 1; off < 1024; off <<= 1) {
        int v = s[t];
        int u = (t >= off) ? s[t - off] : 0;
        __syncthreads();
        s[t] = v + u;
        __syncthreads();
    }
    int excl = (t > 0) ? s[t - 1] : 0;
    #pragma unroll
    for (int i = 0; i < CH; ++i)
        if (base + i < NNODES) d_offs[base + i] = excl + loc[i];
    if (t == 1023) d_offs[NNODES] = s[1023];
}
__global__ void fill_kernel(const int* __restrict__ receivers) {
    int e = blockIdx.x * blockDim.x + threadIdx.x;
    if (e < E_TOTAL) {
        int r = receivers[e];
        int pos = atomicAdd(&d_cur[r], 1);
        d_eids[d_offs[r] + pos] = e;
    }
}

// physical byte of logical k within a 160B row (k-pair permuted layout)
__device__ __host__ __forceinline__ int physk(int k) {
    return ((k >> 4) * 32) + (((k & 7) >> 1) * 8) + (((k >> 3) & 1) * 4) + ((k & 1) * 2);
}

__global__ void bprep_kernel(const float* __restrict__ W1,
                             const float* __restrict__ W2,
                             const float* __restrict__ W3)
{
    int c = blockIdx.x;
    for (int idx = threadIdx.x; idx < 4096; idx += blockDim.x) {
        int n = idx >> 6, k = idx & 63;
        float v;
        if (c < 2)       v = W1[(c * 64 + k) * 64 + n];
        else if (c == 2) v = W2[k * 64 + n];
        else             v = W3[k * 320 + (c - 3) * 64 + n];
        __nv_bfloat16 h = __float2bfloat16(v);
        __nv_bfloat16 l = __float2bfloat16(v - __bfloat162float(h));
        int pb = n * 160 + physk(k);
        *(__nv_bfloat16*)(&BimgP[c][pb])         = h;
        *(__nv_bfloat16*)(&BimgP[c][10240 + pb]) = l;
    }
}

// ---------------- MLP (HMMA) — round-14 validated structure, fp32 F
#define AS_HI 0
#define AS_LO 20480
#define BSL0  40960
#define BSL1  61440
#define BLO   10240
#define SPS_O 81920
#define SPR_O 82432
#define SMB   82944

__device__ __forceinline__ void copyB(char* sm_, int slot, int chunk, int tid) {
    const uint4* s = (const uint4*)BimgP[chunk];
    #pragma unroll
    for (int i = 0; i < 5; ++i) {
        int lin = tid + 256 * i;
        *(uint4*)(sm_ + slot + lin * 16) = s[lin];
    }
}

__device__ __forceinline__ void splitX(char* sm_, const float4* __restrict__ dp,
                                       int base, int tid, int ch) {
    int row = tid >> 1, h = tid & 1;
    char* hrow = sm_ + AS_HI + row * 160;
    char* lrow = sm_ + AS_LO + row * 160;
    #pragma unroll
    for (int j = 0; j < 8; ++j) {
        float4 v = dp[(size_t)(base + row) * 32 + ch * 16 + h * 8 + j];
        u32 h0, l0, h1, l1;
        split2(v.x, v.y, h0, l0);
        split2(v.z, v.w, h1, l1);
        int p = (h * 2 + (j >> 2)) * 32 + (j & 1) * 16 + ((j >> 1) & 1) * 4;
        *(u32*)(hrow + p)     = h0;
        *(u32*)(hrow + p + 8) = h1;
        *(u32*)(lrow + p)     = l0;
        *(u32*)(lrow + p + 8) = l1;
    }
}

__device__ __forceinline__ void gemm_h(const char* sm_, int bslot,
                                       int ao, int bbase, float d[8][4]) {
    #pragma unroll
    for (int ks = 0; ks < 4; ++ks) {
        const int ko = ks * 32;
        uint2 aH0 = *(const uint2*)(sm_ + AS_HI + ao + ko);
        uint2 aH1 = *(const uint2*)(sm_ + AS_HI + ao + 1280 + ko);
        uint2 aL0 = *(const uint2*)(sm_ + AS_LO + ao + ko);
        uint2 aL1 = *(const uint2*)(sm_ + AS_LO + ao + 1280 + ko);
        uint2 bh[8], bl[8];
        #pragma unroll
        for (int nt = 0; nt < 8; ++nt) {
            bh[nt] = *(const uint2*)(sm_ + bslot + bbase + nt * 1280 + ko);
            bl[nt] = *(const uint2*)(sm_ + bslot + BLO + bbase + nt * 1280 + ko);
        }
        #pragma unroll
        for (int nt = 0; nt < 8; ++nt)
            hmma(d[nt][0], d[nt][1], d[nt][2], d[nt][3],
                 aH0.x, aH1.x, aH0.y, aH1.y, bh[nt].x, bh[nt].y);
        #pragma unroll
        for (int nt = 0; nt < 8; ++nt)
            hmma(d[nt][0], d[nt][1], d[nt][2], d[nt][3],
                 aH0.x, aH1.x, aH0.y, aH1.y, bl[nt].x, bl[nt].y);
        #pragma unroll
        for (int nt = 0; nt < 8; ++nt)
            hmma(d[nt][0], d[nt][1], d[nt][2], d[nt][3],
                 aL0.x, aL1.x, aL0.y, aL1.y, bh[nt].x, bh[nt].y);
    }
}

__device__ __forceinline__ void epi_ln(float d[8][4], char* sm_,
                                       int rowA_b, int rowB_b, int lane,
                                       const float* __restrict__ g,
                                       const float* __restrict__ be) {
    const int t2 = (lane & 3) * 2;
    float sa = 0, qa = 0, sb = 0, qb = 0;
    #pragma unroll
    for (int nt = 0; nt < 8; ++nt) {
        sa += d[nt][0] + d[nt][1]; qa += d[nt][0] * d[nt][0] + d[nt][1] * d[nt][1];
        sb += d[nt][2] + d[nt][3]; qb += d[nt][2] * d[nt][2] + d[nt][3] * d[nt][3];
    }
    #pragma unroll
    for (int o = 1; o <= 2; o <<= 1) {
        sa += __shfl_xor_sync(0xffffffffu, sa, o);
        qa += __shfl_xor_sync(0xffffffffu, qa, o);
        sb += __shfl_xor_sync(0xffffffffu, sb, o);
        qb += __shfl_xor_sync(0xffffffffu, qb, o);
    }
    float mua = sa * (1.0f / 64.0f), mub = sb * (1.0f / 64.0f);
    float ra = rsqrtf(fmaxf(qa * (1.0f / 64.0f) - mua * mua, 0.0f) + 1e-5f);
    float rb = rsqrtf(fmaxf(qb * (1.0f / 64.0f) - mub * mub, 0.0f) + 1e-5f);
    #pragma unroll
    for (int nt = 0; nt < 8; ++nt) {
        int col = nt * 8 + t2;
        float2 gv = *(const float2*)(g + col);
        float2 bv = *(const float2*)(be + col);
        float x0 = (d[nt][0] - mua) * ra * gv.x + bv.x;
        float x1 = (d[nt][1] - mua) * ra * gv.y + bv.y;
        float y0 = (d[nt][2] - mub) * rb * gv.x + bv.x;
        float y1 = (d[nt][3] - mub) * rb * gv.y + bv.y;
        x0 = x0 / (1.0f + __expf(-x0));
        x1 = x1 / (1.0f + __expf(-x1));
        y0 = y0 / (1.0f + __expf(-y0));
        y1 = y1 / (1.0f + __expf(-y1));
        int p = (nt >> 1) * 32 + (lane & 3) * 8 + (nt & 1) * 4;
        u32 hi, lo;
        split2(x0, x1, hi, lo);
        *(u32*)(sm_ + AS_HI + rowA_b + p) = hi;
        *(u32*)(sm_ + AS_LO + rowA_b + p) = lo;
        split2(y0, y1, hi, lo);
        *(u32*)(sm_ + AS_HI + rowB_b + p) = hi;
        *(u32*)(sm_ + AS_LO + rowB_b + p) = lo;
    }
}

__global__ __launch_bounds__(256, 2)
void mlp_kernel(const int*   __restrict__ species,
                const float* __restrict__ dist,
                const int*   __restrict__ senders,
                const int*   __restrict__ receivers,
                const float* __restrict__ g1, const float* __restrict__ be1,
                const float* __restrict__ b2,
                const float* __restrict__ g2, const float* __restrict__ be2,
                const float* __restrict__ b3)
{
    extern __shared__ __align__(16) char sm_[];
    int* spS = (int*)(sm_ + SPS_O);
    int* spR = (int*)(sm_ + SPR_O);

    const int tid  = threadIdx.x;
    const int w    = tid >> 5;
    const int lane = tid & 31;
    const int g    = lane >> 2;
    const int jl   = lane & 3;
    const int t2   = jl * 2;
    const int base = blockIdx.x * T1;
    const int rA   = 16 * w + g;
    const int rB   = rA + 8;
    const int ao   = rA * 160 + jl * 8;
    const int bbase = g * 160 + jl * 8;
    const float4* dp = (const float4*)dist;

    copyB(sm_, BSL0, 0, tid);
    copyB(sm_, BSL1, 1, tid);
    if (tid < T1) {
        spS[tid] = species[senders[base + tid]];
        spR[tid] = species[receivers[base + tid]];
    }
    splitX(sm_, dp, base, tid, 0);
    __syncthreads();

    float d[8][4];
    {
        int ssa = spS[rA], sra = spR[rA], ssb = spS[rB], srb = spR[rB];
        #pragma unroll
        for (int nt = 0; nt < 8; ++nt) {
            int col = nt * 8 + t2;
            float2 s1 = *(const float2*)(SPb + ssa * 64 + col);
            float2 r1 = *(const float2*)(RPb + sra * 64 + col);
            float2 s2 = *(const float2*)(SPb + ssb * 64 + col);
            float2 r2 = *(const float2*)(RPb + srb * 64 + col);
            d[nt][0] = s1.x + r1.x; d[nt][1] = s1.y + r1.y;
            d[nt][2] = s2.x + r2.x; d[nt][3] = s2.y + r2.y;
        }
    }
    gemm_h(sm_, BSL0, ao, bbase, d);
    __syncthreads();
    splitX(sm_, dp, base, tid, 1);
    __syncthreads();
    gemm_h(sm_, BSL1, ao, bbase, d);
    __syncthreads();

    epi_ln(d, sm_, rA * 160, rB * 160, lane, g1, be1);
    copyB(sm_, BSL0, 2, tid);
    __syncthreads();

    #pragma unroll
    for (int nt = 0; nt < 8; ++nt)
        d[nt][0] = d[nt][1] = d[nt][2] = d[nt][3] = 0.0f;
    gemm_h(sm_, BSL0, ao, bbase, d);
    __syncthreads();
    #pragma unroll
    for (int nt = 0; nt < 8; ++nt) {
        int col = nt * 8 + t2;
        float2 bb = *(const float2*)(b2 + col);
        d[nt][0] += bb.x; d[nt][1] += bb.y;
        d[nt][2] += bb.x; d[nt][3] += bb.y;
    }
    epi_ln(d, sm_, rA * 160, rB * 160, lane, g2, be2);
    copyB(sm_, BSL1, 3, tid);
    __syncthreads();

    float* fA = F_buf + (size_t)(base + rA) * 320;
    float* fB = F_buf + (size_t)(base + rB) * 320;
    for (int m = 0; m < 5; ++m) {
        int slot = (m & 1) ? BSL0 : BSL1;
        #pragma unroll
        for (int nt = 0; nt < 8; ++nt)
            d[nt][0] = d[nt][1] = d[nt][2] = d[nt][3] = 0.0f;
        gemm_h(sm_, slot, ao, bbase, d);
        if (m < 4)
            copyB(sm_, (m & 1) ? BSL1 : BSL0, 3 + m + 1, tid);
        #pragma unroll
        for (int nt = 0; nt < 8; ++nt) {
            int col = m * 64 + nt * 8 + t2;
            float2 bb = *(const float2*)(b3 + col);
            *(float2*)(fA + col) = make_float2(d[nt][0] + bb.x, d[nt][1] + bb.y);
            *(float2*)(fB + col) = make_float2(d[nt][2] + bb.x, d[nt][3] + bb.y);
        }
        if (m < 4) __syncthreads();
    }
}

// ---------------- wigner gather: 2 warps per node (interleaved edges) + smem combine
__global__ __launch_bounds__(256)
void wigner_gather(const float* __restrict__ wig,
                   const float* __restrict__ env,
                   float* __restrict__ out)
{
    __shared__ ull wbp[8][25 * 8];
    __shared__ ull red[4][32][FULLC];     // half-1 accumulators
    const int tid  = threadIdx.x;
    const int lane = tid & 31;
    const int warp = tid >> 5;
    const int pair = warp >> 1;           // 0..3
    const int half = warp & 1;
    const int node = blockIdx.x * 4 + pair;   // 3125 * 4 = 12500 exactly

    ull acc[FULLC];
    #pragma unroll
    for (int f = 0; f < FULLC; ++f) acc[f] = 0ull;

    const int beg = d_offs[node];
    const int end = d_offs[node + 1];
    ull* wp = wbp[warp];

    const int f0 = (lane +  0) / 5,  m0 = (lane +  0) - 5 * f0;
    const int f1 = (lane + 32) / 5,  m1 = (lane + 32) - 5 * f1;
    const int f2 = (lane + 64) / 5,  m2 = (lane + 64) - 5 * f2;
    const int f3 = (lane + 96) / 5,  m3 = (lane + 96) - 5 * f3;

    float wrv0 = 0, wrv1 = 0, wrv2 = 0, wrv3 = 0, scv = 0;
    ull fr[5] = {0, 0, 0, 0, 0};

    auto load_raw = [&](int e) {
        scv = env[e] * 0.2f;
        const float* wr = wig + (size_t)e * (FULLC * MALL);
        wrv0 = wr[f0 * MALL + m0];
        wrv1 = wr[f1 * MALL + m1];
        wrv2 = wr[f2 * MALL + m2];
        if (lane < 29) wrv3 = wr[f3 * MALL + m3];
        const ull* fp = (const ull*)(F_buf + (size_t)e * 320 + 2 * lane);
        fr[0] = fp[0]; fr[1] = fp[32]; fr[2] = fp[64]; fr[3] = fp[96]; fr[4] = fp[128];
    };

    int idx0 = beg + half;
    if (idx0 < end) load_raw(d_eids[idx0]);

    for (int idx = idx0; idx < end; idx += 2) {
        wp[f0 * 8 + m0] = pack2(wrv0 * scv);
        wp[f1 * 8 + m1] = pack2(wrv1 * scv);
        wp[f2 * 8 + m2] = pack2(wrv2 * scv);
        if (lane < 29) wp[f3 * 8 + m3] = pack2(wrv3 * scv);
        ull fc0 = fr[0], fc1 = fr[1], fc2 = fr[2], fc3 = fr[3], fc4 = fr[4];
        __syncwarp();

        if (idx + 2 < end) load_raw(d_eids[idx + 2]);

        #pragma unroll
        for (int f = 0; f < FULLC; ++f) {
            ulonglong2 wA = *(const ulonglong2*)(wp + f * 8);
            ulonglong2 wB = *(const ulonglong2*)(wp + f * 8 + 2);
            ull w4 = wp[f * 8 + 4];
            ull r = acc[f];
            fma2(r, wA.x, fc0);
            fma2(r, wA.y, fc1);
            fma2(r, wB.x, fc2);
            fma2(r, wB.y, fc3);
            fma2(r, w4,   fc4);
            acc[f] = r;
        }
        __syncwarp();
    }

    // combine halves
    if (half == 1) {
        #pragma unroll
        for (int f = 0; f < FULLC; ++f) red[pair][lane][f] = acc[f];
    }
    __syncthreads();
    if (half == 0) {
        float* ob = out + (size_t)node * 1600 + 2 * lane;
        #pragma unroll
        for (int f = 0; f < FULLC; ++f) {
            float2 rv = unpk(add2(acc[f], red[pair][lane][f]));
            *(float2*)(ob + f * 64) = rv;
        }
        if (lane == 0) { d_cnt[node] = 0; d_cur[node] = 0; }
    }
}

extern "C" void kernel_launch(void* const* d_in, const int* in_sizes, int n_in,
                              void* d_out, int out_size)
{
    const int*   species   = (const int*)  d_in[0];
    const float* dist      = (const float*)d_in[1];
    const int*   senders   = (const int*)  d_in[2];
    const int*   receivers = (const int*)  d_in[3];
    const float* wig       = (const float*)d_in[4];
    const float* env       = (const float*)d_in[5];
    const float* semb      = (const float*)d_in[6];
    const float* remb      = (const float*)d_in[7];
    const float* W1  = (const float*)d_in[8];
    const float* b1  = (const float*)d_in[9];
    const float* g1  = (const float*)d_in[10];
    const float* be1 = (const float*)d_in[11];
    const float* W2  = (const float*)d_in[12];
    const float* b2  = (const float*)d_in[13];
    const float* g2  = (const float*)d_in[14];
    const float* be2 = (const float*)d_in[15];
    const float* W3  = (const float*)d_in[16];
    const float* b3  = (const float*)d_in[17];
    float* out = (float*)d_out;

    cudaFuncSetAttribute(mlp_kernel,
                         cudaFuncAttributeMaxDynamicSharedMemorySize, SMB);

    const int SPBLK = (NSPEC * 64 + 255) / 256;
    bprep_kernel<<<8, 256>>>(W1, W2, W3);
    prep_kernel<<<SPBLK + (E_TOTAL + 255) / 256, 256>>>(receivers, semb, remb, W1, b1);
    scan_kernel<<<1, 1024>>>();
    fill_kernel<<<(E_TOTAL + 255) / 256, 256>>>(receivers);
    mlp_kernel<<<NTILES, 256, SMB>>>(
        species, dist, senders, receivers, g1, be1, b2, g2, be2, b3);
    wigner_gather<<<(NNODES + 3) / 4, 256>>>(wig, env, out);
}

// round 17
// speedup vs baseline: 1.2142x; 1.2142x over previous
#include <cuda_runtime.h>
#include <cuda_bf16.h>
#include <math.h>

#define E_TOTAL 400000
#define NNODES  12500
#define T1      128
#define NTILES  3125
#define FULLC   25
#define MALL    19
#define NSPEC   90

typedef unsigned long long ull;
typedef unsigned int u32;

// ---------------- device scratch (static, no allocs)
__device__ float F_buf[(size_t)E_TOTAL * 320];
__device__ int   d_cnt[NNODES];
__device__ int   d_cur[NNODES];
__device__ int   d_offs[NNODES + 1];
__device__ int   d_eids[E_TOTAL];
__device__ float SPb[NSPEC * 64];
__device__ float RPb[NSPEC * 64];
__device__ __align__(16) unsigned char BimgP[8][20480];

// ---------------- f32x2 helpers
__device__ __forceinline__ ull pack2(float x) {
    ull r; asm("mov.b64 %0,{%1,%1};" : "=l"(r) : "f"(x)); return r;
}
__device__ __forceinline__ void fma2(ull& d, ull a, ull b) {
    asm("fma.rn.f32x2 %0,%1,%2,%0;" : "+l"(d) : "l"(a), "l"(b));
}
__device__ __forceinline__ float2 unpk(ull v) {
    float2 o; asm("mov.b64 {%0,%1},%2;" : "=f"(o.x), "=f"(o.y) : "l"(v)); return o;
}

// ---------------- HMMA helpers
__device__ __forceinline__ void hmma(float& d0, float& d1, float& d2, float& d3,
                                     u32 a0, u32 a1, u32 a2, u32 a3,
                                     u32 b0, u32 b1) {
    asm volatile("mma.sync.aligned.m16n8k16.row.col.f32.bf16.bf16.f32 "
        "{%0,%1,%2,%3}, {%4,%5,%6,%7}, {%8,%9}, {%0,%1,%2,%3};"
        : "+f"(d0), "+f"(d1), "+f"(d2), "+f"(d3)
        : "r"(a0), "r"(a1), "r"(a2), "r"(a3), "r"(b0), "r"(b1));
}
__device__ __forceinline__ void split2(float x, float y, u32& hi, u32& lo) {
    __nv_bfloat16 hx = __float2bfloat16(x);
    __nv_bfloat16 hy = __float2bfloat16(y);
    __nv_bfloat16 lx = __float2bfloat16(x - __bfloat162float(hx));
    __nv_bfloat16 ly = __float2bfloat16(y - __bfloat162float(hy));
    hi = (u32)__bfloat16_as_ushort(hx) | ((u32)__bfloat16_as_ushort(hy) << 16);
    lo = (u32)__bfloat16_as_ushort(lx) | ((u32)__bfloat16_as_ushort(ly) << 16);
}

// physical byte of logical k within a 160B row (k-pair permuted layout)
__device__ __host__ __forceinline__ int physk(int k) {
    return ((k >> 4) * 32) + (((k & 7) >> 1) * 8) + (((k >> 3) & 1) * 4) + ((k & 1) * 2);
}

// ---------------- fused prelude: weight image + species projection + histogram
__global__ void prep_kernel(const int* __restrict__ receivers,
                            const float* __restrict__ semb,
                            const float* __restrict__ remb,
                            const float* __restrict__ W1,
                            const float* __restrict__ b1,
                            const float* __restrict__ W2,
                            const float* __restrict__ W3)
{
    const int SPBLK = (NSPEC * 64 + 255) / 256;   // 23
    if (blockIdx.x < 8) {
        // weight image: transpose + hi/lo split + permute
        int c = blockIdx.x;
        for (int idx = threadIdx.x; idx < 4096; idx += blockDim.x) {
            int n = idx >> 6, k = idx & 63;
            float v;
            if (c < 2)       v = W1[(c * 64 + k) * 64 + n];
            else if (c == 2) v = W2[k * 64 + n];
            else             v = W3[k * 320 + (c - 3) * 64 + n];
            __nv_bfloat16 h = __float2bfloat16(v);
            __nv_bfloat16 l = __float2bfloat16(v - __bfloat162float(h));
            int pb = n * 160 + physk(k);
            *(__nv_bfloat16*)(&BimgP[c][pb])         = h;
            *(__nv_bfloat16*)(&BimgP[c][10240 + pb]) = l;
        }
    } else if (blockIdx.x < 8 + SPBLK) {
        int idx = (blockIdx.x - 8) * 256 + threadIdx.x;
        if (idx < NSPEC * 64) {
            int s = idx >> 6, c = idx & 63;
            float sp = b1[c], rp = 0.0f;
            #pragma unroll 8
            for (int k = 0; k < 64; ++k) {
                sp += semb[s * 64 + k] * W1[(128 + k) * 64 + c];
                rp += remb[s * 64 + k] * W1[(192 + k) * 64 + c];
            }
            SPb[idx] = sp;
            RPb[idx] = rp;
        }
    } else {
        int e = (blockIdx.x - 8 - SPBLK) * 256 + threadIdx.x;
        if (e < E_TOTAL) atomicAdd(&d_cnt[receivers[e]], 1);
    }
}

// warp-shuffle scan: 1024 threads, 2 CTA barriers
__global__ void scan_kernel() {
    __shared__ int wsum[32];
    const int CH = (NNODES + 1023) / 1024;   // 13
    int t = threadIdx.x, lane = t & 31, w = t >> 5;
    int base = t * CH;
    int loc[CH];
    int sum = 0;
    #pragma unroll
    for (int i = 0; i < CH; ++i) {
        int v = (base + i < NNODES) ? d_cnt[base + i] : 0;
        loc[i] = sum; sum += v;
    }
    int incl = sum;
    #pragma unroll
    for (int o = 1; o < 32; o <<= 1) {
        int u = __shfl_up_sync(0xffffffffu, incl, o);
        if (lane >= o) incl += u;
    }
    if (lane == 31) wsum[w] = incl;
    __syncthreads();
    if (w == 0) {
        int v = wsum[lane];
        int ws = v;
        #pragma unroll
        for (int o = 1; o < 32; o <<= 1) {
            int u = __shfl_up_sync(0xffffffffu, ws, o);
            if (lane >= o) ws += u;
        }
        wsum[lane] = ws - v;    // exclusive warp offset
    }
    __syncthreads();
    int excl = wsum[w] + incl - sum;
    #pragma unroll
    for (int i = 0; i < CH; ++i)
        if (base + i < NNODES) d_offs[base + i] = excl + loc[i];
    if (t == 1023) d_offs[NNODES] = excl + sum;
}
__global__ void fill_kernel(const int* __restrict__ receivers) {
    int e = blockIdx.x * blockDim.x + threadIdx.x;
    if (e < E_TOTAL) {
        int r = receivers[e];
        int pos = atomicAdd(&d_cur[r], 1);
        d_eids[d_offs[r] + pos] = e;
    }
}

// ---------------- MLP (HMMA) — round-14 validated
#define AS_HI 0
#define AS_LO 20480
#define BSL0  40960
#define BSL1  61440
#define BLO   10240
#define SPS_O 81920
#define SPR_O 82432
#define SMB   82944

__device__ __forceinline__ void copyB(char* sm_, int slot, int chunk, int tid) {
    const uint4* s = (const uint4*)BimgP[chunk];
    #pragma unroll
    for (int i = 0; i < 5; ++i) {
        int lin = tid + 256 * i;
        *(uint4*)(sm_ + slot + lin * 16) = s[lin];
    }
}

__device__ __forceinline__ void splitX(char* sm_, const float4* __restrict__ dp,
                                       int base, int tid, int ch) {
    int row = tid >> 1, h = tid & 1;
    char* hrow = sm_ + AS_HI + row * 160;
    char* lrow = sm_ + AS_LO + row * 160;
    #pragma unroll
    for (int j = 0; j < 8; ++j) {
        float4 v = dp[(size_t)(base + row) * 32 + ch * 16 + h * 8 + j];
        u32 h0, l0, h1, l1;
        split2(v.x, v.y, h0, l0);
        split2(v.z, v.w, h1, l1);
        int p = (h * 2 + (j >> 2)) * 32 + (j & 1) * 16 + ((j >> 1) & 1) * 4;
        *(u32*)(hrow + p)     = h0;
        *(u32*)(hrow + p + 8) = h1;
        *(u32*)(lrow + p)     = l0;
        *(u32*)(lrow + p + 8) = l1;
    }
}

__device__ __forceinline__ void gemm_h(const char* sm_, int bslot,
                                       int ao, int bbase, float d[8][4]) {
    #pragma unroll
    for (int ks = 0; ks < 4; ++ks) {
        const int ko = ks * 32;
        uint2 aH0 = *(const uint2*)(sm_ + AS_HI + ao + ko);
        uint2 aH1 = *(const uint2*)(sm_ + AS_HI + ao + 1280 + ko);
        uint2 aL0 = *(const uint2*)(sm_ + AS_LO + ao + ko);
        uint2 aL1 = *(const uint2*)(sm_ + AS_LO + ao + 1280 + ko);
        uint2 bh[8], bl[8];
        #pragma unroll
        for (int nt = 0; nt < 8; ++nt) {
            bh[nt] = *(const uint2*)(sm_ + bslot + bbase + nt * 1280 + ko);
            bl[nt] = *(const uint2*)(sm_ + bslot + BLO + bbase + nt * 1280 + ko);
        }
        #pragma unroll
        for (int nt = 0; nt < 8; ++nt)
            hmma(d[nt][0], d[nt][1], d[nt][2], d[nt][3],
                 aH0.x, aH1.x, aH0.y, aH1.y, bh[nt].x, bh[nt].y);
        #pragma unroll
        for (int nt = 0; nt < 8; ++nt)
            hmma(d[nt][0], d[nt][1], d[nt][2], d[nt][3],
                 aH0.x, aH1.x, aH0.y, aH1.y, bl[nt].x, bl[nt].y);
        #pragma unroll
        for (int nt = 0; nt < 8; ++nt)
            hmma(d[nt][0], d[nt][1], d[nt][2], d[nt][3],
                 aL0.x, aL1.x, aL0.y, aL1.y, bh[nt].x, bh[nt].y);
    }
}

__device__ __forceinline__ void epi_ln(float d[8][4], char* sm_,
                                       int rowA_b, int rowB_b, int lane,
                                       const float* __restrict__ g,
                                       const float* __restrict__ be) {
    const int t2 = (lane & 3) * 2;
    float sa = 0, qa = 0, sb = 0, qb = 0;
    #pragma unroll
    for (int nt = 0; nt < 8; ++nt) {
        sa += d[nt][0] + d[nt][1]; qa += d[nt][0] * d[nt][0] + d[nt][1] * d[nt][1];
        sb += d[nt][2] + d[nt][3]; qb += d[nt][2] * d[nt][2] + d[nt][3] * d[nt][3];
    }
    #pragma unroll
    for (int o = 1; o <= 2; o <<= 1) {
        sa += __shfl_xor_sync(0xffffffffu, sa, o);
        qa += __shfl_xor_sync(0xffffffffu, qa, o);
        sb += __shfl_xor_sync(0xffffffffu, sb, o);
        qb += __shfl_xor_sync(0xffffffffu, qb, o);
    }
    float mua = sa * (1.0f / 64.0f), mub = sb * (1.0f / 64.0f);
    float ra = rsqrtf(fmaxf(qa * (1.0f / 64.0f) - mua * mua, 0.0f) + 1e-5f);
    float rb = rsqrtf(fmaxf(qb * (1.0f / 64.0f) - mub * mub, 0.0f) + 1e-5f);
    #pragma unroll
    for (int nt = 0; nt < 8; ++nt) {
        int col = nt * 8 + t2;
        float2 gv = *(const float2*)(g + col);
        float2 bv = *(const float2*)(be + col);
        float x0 = (d[nt][0] - mua) * ra * gv.x + bv.x;
        float x1 = (d[nt][1] - mua) * ra * gv.y + bv.y;
        float y0 = (d[nt][2] - mub) * rb * gv.x + bv.x;
        float y1 = (d[nt][3] - mub) * rb * gv.y + bv.y;
        x0 = x0 / (1.0f + __expf(-x0));
        x1 = x1 / (1.0f + __expf(-x1));
        y0 = y0 / (1.0f + __expf(-y0));
        y1 = y1 / (1.0f + __expf(-y1));
        int p = (nt >> 1) * 32 + (lane & 3) * 8 + (nt & 1) * 4;
        u32 hi, lo;
        split2(x0, x1, hi, lo);
        *(u32*)(sm_ + AS_HI + rowA_b + p) = hi;
        *(u32*)(sm_ + AS_LO + rowA_b + p) = lo;
        split2(y0, y1, hi, lo);
        *(u32*)(sm_ + AS_HI + rowB_b + p) = hi;
        *(u32*)(sm_ + AS_LO + rowB_b + p) = lo;
    }
}

__global__ __launch_bounds__(256, 2)
void mlp_kernel(const int*   __restrict__ species,
                const float* __restrict__ dist,
                const int*   __restrict__ senders,
                const int*   __restrict__ receivers,
                const float* __restrict__ g1, const float* __restrict__ be1,
                const float* __restrict__ b2,
                const float* __restrict__ g2, const float* __restrict__ be2,
                const float* __restrict__ b3)
{
    extern __shared__ __align__(16) char sm_[];
    int* spS = (int*)(sm_ + SPS_O);
    int* spR = (int*)(sm_ + SPR_O);

    const int tid  = threadIdx.x;
    const int w    = tid >> 5;
    const int lane = tid & 31;
    const int g    = lane >> 2;
    const int jl   = lane & 3;
    const int t2   = jl * 2;
    const int base = blockIdx.x * T1;
    const int rA   = 16 * w + g;
    const int rB   = rA + 8;
    const int ao   = rA * 160 + jl * 8;
    const int bbase = g * 160 + jl * 8;
    const float4* dp = (const float4*)dist;

    copyB(sm_, BSL0, 0, tid);
    copyB(sm_, BSL1, 1, tid);
    if (tid < T1) {
        spS[tid] = species[senders[base + tid]];
        spR[tid] = species[receivers[base + tid]];
    }
    splitX(sm_, dp, base, tid, 0);
    __syncthreads();

    float d[8][4];
    {
        int ssa = spS[rA], sra = spR[rA], ssb = spS[rB], srb = spR[rB];
        #pragma unroll
        for (int nt = 0; nt < 8; ++nt) {
            int col = nt * 8 + t2;
            float2 s1 = *(const float2*)(SPb + ssa * 64 + col);
            float2 r1 = *(const float2*)(RPb + sra * 64 + col);
            float2 s2 = *(const float2*)(SPb + ssb * 64 + col);
            float2 r2 = *(const float2*)(RPb + srb * 64 + col);
            d[nt][0] = s1.x + r1.x; d[nt][1] = s1.y + r1.y;
            d[nt][2] = s2.x + r2.x; d[nt][3] = s2.y + r2.y;
        }
    }
    gemm_h(sm_, BSL0, ao, bbase, d);
    __syncthreads();
    splitX(sm_, dp, base, tid, 1);
    __syncthreads();
    gemm_h(sm_, BSL1, ao, bbase, d);
    __syncthreads();

    epi_ln(d, sm_, rA * 160, rB * 160, lane, g1, be1);
    copyB(sm_, BSL0, 2, tid);
    __syncthreads();

    #pragma unroll
    for (int nt = 0; nt < 8; ++nt)
        d[nt][0] = d[nt][1] = d[nt][2] = d[nt][3] = 0.0f;
    gemm_h(sm_, BSL0, ao, bbase, d);
    __syncthreads();
    #pragma unroll
    for (int nt = 0; nt < 8; ++nt) {
        int col = nt * 8 + t2;
        float2 bb = *(const float2*)(b2 + col);
        d[nt][0] += bb.x; d[nt][1] += bb.y;
        d[nt][2] += bb.x; d[nt][3] += bb.y;
    }
    epi_ln(d, sm_, rA * 160, rB * 160, lane, g2, be2);
    copyB(sm_, BSL1, 3, tid);
    __syncthreads();

    float* fA = F_buf + (size_t)(base + rA) * 320;
    float* fB = F_buf + (size_t)(base + rB) * 320;
    for (int m = 0; m < 5; ++m) {
        int slot = (m & 1) ? BSL0 : BSL1;
        #pragma unroll
        for (int nt = 0; nt < 8; ++nt)
            d[nt][0] = d[nt][1] = d[nt][2] = d[nt][3] = 0.0f;
        gemm_h(sm_, slot, ao, bbase, d);
        if (m < 4)
            copyB(sm_, (m & 1) ? BSL1 : BSL0, 3 + m + 1, tid);
        #pragma unroll
        for (int nt = 0; nt < 8; ++nt) {
            int col = m * 64 + nt * 8 + t2;
            float2 bb = *(const float2*)(b3 + col);
            *(float2*)(fA + col) = make_float2(d[nt][0] + bb.x, d[nt][1] + bb.y);
            *(float2*)(fB + col) = make_float2(d[nt][2] + bb.x, d[nt][3] + bb.y);
        }
        if (m < 4) __syncthreads();
    }
}

// ---------------- wigner gather: 1 warp/node, 128-thr CTAs, double-buffered wp
__global__ __launch_bounds__(128)
void wigner_gather(const float* __restrict__ wig,
                   const float* __restrict__ env,
                   float* __restrict__ out)
{
    __shared__ ull wbp[4][2][25 * 8];
    const int tid  = threadIdx.x;
    const int lane = tid & 31;
    const int warp = tid >> 5;
    const int node = blockIdx.x * 4 + warp;   // 3125 * 4 = 12500 exactly

    ull acc[FULLC];
    #pragma unroll
    for (int f = 0; f < FULLC; ++f) acc[f] = 0ull;

    const int beg = d_offs[node];
    const int end = d_offs[node + 1];

    const int f0 = (lane +  0) / 5,  m0 = (lane +  0) - 5 * f0;
    const int f1 = (lane + 32) / 5,  m1 = (lane + 32) - 5 * f1;
    const int f2 = (lane + 64) / 5,  m2 = (lane + 64) - 5 * f2;
    const int f3 = (lane + 96) / 5,  m3 = (lane + 96) - 5 * f3;

    float wrv0 = 0, wrv1 = 0, wrv2 = 0, wrv3 = 0, scv = 0;
    ull fr[5] = {0, 0, 0, 0, 0};

    auto load_raw = [&](int e) {
        scv = env[e] * 0.2f;
        const float* wr = wig + (size_t)e * (FULLC * MALL);
        wrv0 = wr[f0 * MALL + m0];
        wrv1 = wr[f1 * MALL + m1];
        wrv2 = wr[f2 * MALL + m2];
        if (lane < 29) wrv3 = wr[f3 * MALL + m3];
        const ull* fp = (const ull*)(F_buf + (size_t)e * 320 + 2 * lane);
        fr[0] = fp[0]; fr[1] = fp[32]; fr[2] = fp[64]; fr[3] = fp[96]; fr[4] = fp[128];
    };

    if (beg < end) load_raw(d_eids[beg]);

    int it = 0;
    for (int idx = beg; idx < end; ++idx, ++it) {
        ull* wp = wbp[warp][it & 1];
        wp[f0 * 8 + m0] = pack2(wrv0 * scv);
        wp[f1 * 8 + m1] = pack2(wrv1 * scv);
        wp[f2 * 8 + m2] = pack2(wrv2 * scv);
        if (lane < 29) wp[f3 * 8 + m3] = pack2(wrv3 * scv);
        ull fc0 = fr[0], fc1 = fr[1], fc2 = fr[2], fc3 = fr[3], fc4 = fr[4];
        // ONE syncwarp per edge: iteration it+2 rewrites this buffer only after
        // the syncwarp of it+1, which every lane reaches only after finishing
        // the reads below (program order) -> no trailing barrier needed.
        __syncwarp();

        if (idx + 1 < end) load_raw(d_eids[idx + 1]);

        #pragma unroll
        for (int f = 0; f < FULLC; ++f) {
            ulonglong2 wA = *(const ulonglong2*)(wp + f * 8);
            ulonglong2 wB = *(const ulonglong2*)(wp + f * 8 + 2);
            ull w4 = wp[f * 8 + 4];
            ull r = acc[f];
            fma2(r, wA.x, fc0);
            fma2(r, wA.y, fc1);
            fma2(r, wB.x, fc2);
            fma2(r, wB.y, fc3);
            fma2(r, w4,   fc4);
            acc[f] = r;
        }
    }

    float* ob = out + (size_t)node * 1600 + 2 * lane;
    #pragma unroll
    for (int f = 0; f < FULLC; ++f) {
        float2 rv = unpk(acc[f]);
        *(float2*)(ob + f * 64) = rv;
    }

    if (lane == 0) { d_cnt[node] = 0; d_cur[node] = 0; }
}

extern "C" void kernel_launch(void* const* d_in, const int* in_sizes, int n_in,
                              void* d_out, int out_size)
{
    const int*   species   = (const int*)  d_in[0];
    const float* dist      = (const float*)d_in[1];
    const int*   senders   = (const int*)  d_in[2];
    const int*   receivers = (const int*)  d_in[3];
    const float* wig       = (const float*)d_in[4];
    const float* env       = (const float*)d_in[5];
    const float* semb      = (const float*)d_in[6];
    const float* remb      = (const float*)d_in[7];
    const float* W1  = (const float*)d_in[8];
    const float* b1  = (const float*)d_in[9];
    const float* g1  = (const float*)d_in[10];
    const float* be1 = (const float*)d_in[11];
    const float* W2  = (const float*)d_in[12];
    const float* b2  = (const float*)d_in[13];
    const float* g2  = (const float*)d_in[14];
    const float* be2 = (const float*)d_in[15];
    const float* W3  = (const float*)d_in[16];
    const float* b3  = (const float*)d_in[17];
    float* out = (float*)d_out;

    cudaFuncSetAttribute(mlp_kernel,
                         cudaFuncAttributeMaxDynamicSharedMemorySize, SMB);

    const int SPBLK = (NSPEC * 64 + 255) / 256;
    prep_kernel<<<8 + SPBLK + (E_TOTAL + 255) / 256, 256>>>(
        receivers, semb, remb, W1, b1, W2, W3);
    scan_kernel<<<1, 1024>>>();
    fill_kernel<<<(E_TOTAL + 255) / 256, 256>>>(receivers);
    mlp_kernel<<<NTILES, 256, SMB>>>(
        species, dist, senders, receivers, g1, be1, b2, g2, be2, b3);
    wigner_gather<<<NNODES / 4, 128>>>(wig, env, out);
}